// round 1
// baseline (speedup 1.0000x reference)
#include <cuda_runtime.h>
#include <cstdint>
#include <cstddef>

#define B_DIM 64
#define S_DIM 512
#define E_DIM 256
#define D_DIM 512

// Combined conv weights, layout [tap][D][E]
__device__ float g_Wc [6 * D_DIM * E_DIM];   // interior, taps delta = -2..3
__device__ float g_Wc1[5 * D_DIM * E_DIM];   // i == 1,  taps delta = -1..3
__device__ float g_Wc0[4 * D_DIM * E_DIM];   // i == 0,  taps delta =  0..3
__device__ float g_bias[3 * D_DIM];          // [class0, class1, interior]

// ---------------------------------------------------------------------------
// Preprocessing: build combined weights from W1..W4.
// Interior (i>=2): y[i] = sum_delta C_delta x_{i+delta}, where
//   contributions: n-gram n (>=2) contributes W_n[:,:,k] for window shift
//   j in [0, n-2] with delta = k - j. n=1 contributes at delta=0.
// ---------------------------------------------------------------------------
__global__ void preproc_kernel(
    const float* __restrict__ W1, const float* __restrict__ b1,
    const float* __restrict__ W2, const float* __restrict__ b2,
    const float* __restrict__ W3, const float* __restrict__ b3,
    const float* __restrict__ W4, const float* __restrict__ b4)
{
    int idx = blockIdx.x * blockDim.x + threadIdx.x;
    if (idx >= D_DIM * E_DIM) return;
    int d = idx >> 8;   // / E_DIM
    int e = idx & 255;
    (void)e;

    float w1  = W1[idx];
    const float* p2 = W2 + (size_t)idx * 2;
    float w20 = p2[0], w21 = p2[1];
    const float* p3 = W3 + (size_t)idx * 3;
    float w30 = p3[0], w31 = p3[1], w32 = p3[2];
    const float* p4 = W4 + (size_t)idx * 4;
    float w40 = p4[0], w41 = p4[1], w42 = p4[2], w43 = p4[3];

    const size_t st = (size_t)D_DIM * E_DIM;
    // interior: delta = t - 2
    g_Wc[0 * st + idx] = w40;                                        // d=-2: (4,j2,k0)
    g_Wc[1 * st + idx] = w30 + w40 + w41;                            // d=-1
    g_Wc[2 * st + idx] = w1 + w20 + w30 + w31 + w40 + w41 + w42;     // d=0
    g_Wc[3 * st + idx] = w21 + w31 + w32 + w41 + w42 + w43;          // d=1
    g_Wc[4 * st + idx] = w32 + w42 + w43;                            // d=2
    g_Wc[5 * st + idx] = w43;                                        // d=3
    // class i==1: j <= min(n-2,1), delta = t - 1
    g_Wc1[0 * st + idx] = w30 + w40;
    g_Wc1[1 * st + idx] = w1 + w20 + w30 + w31 + w40 + w41;
    g_Wc1[2 * st + idx] = w21 + w31 + w32 + w41 + w42;
    g_Wc1[3 * st + idx] = w32 + w42 + w43;
    g_Wc1[4 * st + idx] = w43;
    // class i==0: j == 0 only, delta = t
    g_Wc0[0 * st + idx] = w1 + w20 + w30 + w40;
    g_Wc0[1 * st + idx] = w21 + w31 + w41;
    g_Wc0[2 * st + idx] = w32 + w42;
    g_Wc0[3 * st + idx] = w43;

    if (e == 0) {
        float B1 = b1[d], B2 = b2[d], B3 = b3[d], B4 = b4[d];
        g_bias[0 * D_DIM + d] = B1 + B2 + B3 + B4;                   // i==0
        g_bias[1 * D_DIM + d] = B1 + B2 + 2.f * B3 + 2.f * B4;       // i==1
        g_bias[2 * D_DIM + d] = B1 + B2 + 2.f * B3 + 3.f * B4;       // interior
    }
}

// ---------------------------------------------------------------------------
// Tap-conv GEMM: y[b, i, d] = bias[d] + sum_t sum_e W[t][d][e] * x[b, i+delta0+t, e]
// Rows r = b * i_count + (i - i_begin), tiled 64 rows x 64 d-cols per block,
// 256 threads, 4x4 microtile per thread, K chunked by (tap, 64-e slice).
// ---------------------------------------------------------------------------
__global__ void __launch_bounds__(256) conv_gemm_kernel(
    const float* __restrict__ x,      // [B, S, E]
    const float* __restrict__ W,      // [T, D, E]
    const float* __restrict__ bias,   // [D]
    float* __restrict__ out,          // [B, S, D]
    int T, int delta0, int i_begin, int i_count)
{
    __shared__ float Xs[64][68];   // [e][m], padded
    __shared__ float Ws[64][68];   // [e][n], padded

    const int tid = threadIdx.x;
    const int tx = tid & 15;       // n-group (4 cols each)
    const int ty = tid >> 4;       // m-group (4 rows each)
    const int rowTile = blockIdx.x * 64;
    const int d0 = blockIdx.y * 64;

    const int le  = tid & 63;      // e within chunk (loader)
    const int lm0 = tid >> 6;      // 0..3 (loader row phase)

    // Precompute global row bases (b*S + i) for the 16 rows this thread loads.
    int rbase[16];
#pragma unroll
    for (int j = 0; j < 16; ++j) {
        int r = rowTile + lm0 + 4 * j;
        int b = r / i_count;
        int i = i_begin + (r - b * i_count);
        rbase[j] = b * S_DIM + i;
    }

    float acc[4][4];
#pragma unroll
    for (int a = 0; a < 4; ++a)
#pragma unroll
        for (int c = 0; c < 4; ++c) acc[a][c] = 0.f;

    for (int t = 0; t < T; ++t) {
        const float* Wt = W + ((size_t)t * D_DIM + d0) * E_DIM;
        const int xoff = delta0 + t;
        for (int ec = 0; ec < E_DIM; ec += 64) {
#pragma unroll
            for (int j = 0; j < 16; ++j) {
                Xs[le][lm0 + 4 * j] =
                    x[(size_t)(rbase[j] + xoff) * E_DIM + ec + le];
            }
#pragma unroll
            for (int j = 0; j < 16; ++j) {
                Ws[le][lm0 + 4 * j] = Wt[(size_t)(lm0 + 4 * j) * E_DIM + ec + le];
            }
            __syncthreads();
#pragma unroll 16
            for (int e = 0; e < 64; ++e) {
                float4 av = *reinterpret_cast<const float4*>(&Xs[e][ty * 4]);
                float4 bv = *reinterpret_cast<const float4*>(&Ws[e][tx * 4]);
                acc[0][0] += av.x * bv.x; acc[0][1] += av.x * bv.y;
                acc[0][2] += av.x * bv.z; acc[0][3] += av.x * bv.w;
                acc[1][0] += av.y * bv.x; acc[1][1] += av.y * bv.y;
                acc[1][2] += av.y * bv.z; acc[1][3] += av.y * bv.w;
                acc[2][0] += av.z * bv.x; acc[2][1] += av.z * bv.y;
                acc[2][2] += av.z * bv.z; acc[2][3] += av.z * bv.w;
                acc[3][0] += av.w * bv.x; acc[3][1] += av.w * bv.y;
                acc[3][2] += av.w * bv.z; acc[3][3] += av.w * bv.w;
            }
            __syncthreads();
        }
    }

    float bs0 = bias[d0 + tx * 4 + 0];
    float bs1 = bias[d0 + tx * 4 + 1];
    float bs2 = bias[d0 + tx * 4 + 2];
    float bs3 = bias[d0 + tx * 4 + 3];

#pragma unroll
    for (int mr = 0; mr < 4; ++mr) {
        int r = rowTile + ty * 4 + mr;
        int b = r / i_count;
        int i = i_begin + (r - b * i_count);
        float4 o;
        o.x = acc[mr][0] + bs0;
        o.y = acc[mr][1] + bs1;
        o.z = acc[mr][2] + bs2;
        o.w = acc[mr][3] + bs3;
        *reinterpret_cast<float4*>(
            &out[((size_t)(b * S_DIM + i)) * D_DIM + d0 + tx * 4]) = o;
    }
}

extern "C" void kernel_launch(void* const* d_in, const int* in_sizes, int n_in,
                              void* d_out, int out_size)
{
    (void)in_sizes; (void)n_in; (void)out_size;
    const float* x  = (const float*)d_in[0];
    const float* W1 = (const float*)d_in[1];
    const float* b1 = (const float*)d_in[2];
    const float* W2 = (const float*)d_in[3];
    const float* b2 = (const float*)d_in[4];
    const float* W3 = (const float*)d_in[5];
    const float* b3 = (const float*)d_in[6];
    const float* W4 = (const float*)d_in[7];
    const float* b4 = (const float*)d_in[8];
    float* out = (float*)d_out;

    float *pWc, *pWc1, *pWc0, *pBias;
    cudaGetSymbolAddress((void**)&pWc,  g_Wc);
    cudaGetSymbolAddress((void**)&pWc1, g_Wc1);
    cudaGetSymbolAddress((void**)&pWc0, g_Wc0);
    cudaGetSymbolAddress((void**)&pBias, g_bias);

    // 1) Build combined weights (tiny)
    preproc_kernel<<<(D_DIM * E_DIM + 255) / 256, 256>>>(W1, b1, W2, b2, W3, b3, W4, b4);

    // 2) Boundary rows i=0 (4 taps) and i=1 (5 taps): 64 rows each
    conv_gemm_kernel<<<dim3(1, D_DIM / 64), 256>>>(x, pWc0, pBias + 0 * D_DIM, out, 4,  0, 0, 1);
    conv_gemm_kernel<<<dim3(1, D_DIM / 64), 256>>>(x, pWc1, pBias + 1 * D_DIM, out, 5, -1, 1, 1);

    // 3) Interior rows i in [2, 256): 6-tap combined conv (64*254 rows)
    conv_gemm_kernel<<<dim3((B_DIM * 254) / 64, D_DIM / 64), 256>>>(
        x, pWc, pBias + 2 * D_DIM, out, 6, -2, 2, 254);

    // 4) Tail rows i in [256, 512): unigram only, W1 is already [1][D][E]
    conv_gemm_kernel<<<dim3((B_DIM * 256) / 64, D_DIM / 64), 256>>>(
        x, W1, b1, out, 1, 0, 256, 256);
}